// round 9
// baseline (speedup 1.0000x reference)
#include <cuda_runtime.h>

// 2-layer GCN: gather aggregation (R5 core) + K-paired f32x2 GEMMs (no pack MOVs).

#define N_NODES 50000
#define DIM_IN 64
#define DIM_HID 128
#define CAP 128

typedef unsigned long long u64;

__device__ __forceinline__ void fma2(u64& d, u64 a, u64 b) {
    asm("fma.rn.f32x2 %0, %1, %2, %3;" : "=l"(d) : "l"(a), "l"(b), "l"(d));
}
__device__ __forceinline__ float2 up(u64 v) {
    float2 f; asm("mov.b64 {%0, %1}, %2;" : "=f"(f.x), "=f"(f.y) : "l"(v)); return f;
}

__device__ int   g_cnt[N_NODES];
__device__ int   g_bucket[N_NODES * CAP];
__device__ float g_dinv[N_NODES];
__device__ float g_z   [N_NODES * DIM_IN];
__device__ float g_h   [N_NODES * DIM_HID];
__device__ float g_y2  [N_NODES * DIM_IN];

// ---------------- build ----------------
__global__ void k_place(const int* __restrict__ src, const int* __restrict__ dst, int e) {
    int i = blockIdx.x * blockDim.x + threadIdx.x;
    if (i < e) {
        int d = dst[i];
        int pos = atomicAdd(&g_cnt[d], 1);
        g_bucket[d * CAP + pos] = src[i];
    }
}
__global__ void k_dinv(int n) {
    int i = blockIdx.x * blockDim.x + threadIdx.x;
    if (i < n) g_dinv[i] = rsqrtf((float)g_cnt[i] + 1.0f);
}

// ---------------- gather aggregation (R5 4-wide core) ----------------
// PRESCALE: acc += dinv[c] * F[c]  (fused y = dinv*x);  FINISH: out = dinv*acc + bias
template <bool PRESCALE, bool FINISH>
__global__ void k_agg(const float* __restrict__ F, float* __restrict__ O,
                      const float* __restrict__ bias, int n) {
    int node = blockIdx.x * 32 + threadIdx.y;
    if (node >= n) return;
    int lane = threadIdx.x;
    const float4* F4 = reinterpret_cast<const float4*>(F);
    const int4* cols4 = reinterpret_cast<const int4*>(g_bucket + node * CAP);
    int cnt = g_cnt[node];
    float di = g_dinv[node];

    float4 acc;
    {
        float4 v = F4[node * 16 + lane];  // self term
        if (PRESCALE) { acc.x = di * v.x; acc.y = di * v.y; acc.z = di * v.z; acc.w = di * v.w; }
        else          { acc = v; }
    }
    int j = 0;
    for (; j + 4 <= cnt; j += 4) {
        int4 c = __ldg(&cols4[j >> 2]);
        float4 u0 = F4[c.x * 16 + lane];
        float4 u1 = F4[c.y * 16 + lane];
        float4 u2 = F4[c.z * 16 + lane];
        float4 u3 = F4[c.w * 16 + lane];
        if (PRESCALE) {
            float s0 = g_dinv[c.x], s1 = g_dinv[c.y], s2 = g_dinv[c.z], s3 = g_dinv[c.w];
            acc.x = fmaf(s0, u0.x, fmaf(s1, u1.x, fmaf(s2, u2.x, fmaf(s3, u3.x, acc.x))));
            acc.y = fmaf(s0, u0.y, fmaf(s1, u1.y, fmaf(s2, u2.y, fmaf(s3, u3.y, acc.y))));
            acc.z = fmaf(s0, u0.z, fmaf(s1, u1.z, fmaf(s2, u2.z, fmaf(s3, u3.z, acc.z))));
            acc.w = fmaf(s0, u0.w, fmaf(s1, u1.w, fmaf(s2, u2.w, fmaf(s3, u3.w, acc.w))));
        } else {
            acc.x += (u0.x + u1.x) + (u2.x + u3.x);
            acc.y += (u0.y + u1.y) + (u2.y + u3.y);
            acc.z += (u0.z + u1.z) + (u2.z + u3.z);
            acc.w += (u0.w + u1.w) + (u2.w + u3.w);
        }
    }
    if (j < cnt) {
        int4 c = __ldg(&cols4[j >> 2]);
        int rem = cnt - j;
        {
            float4 u = F4[c.x * 16 + lane];
            float s = PRESCALE ? g_dinv[c.x] : 1.0f;
            if (PRESCALE) { acc.x = fmaf(s,u.x,acc.x); acc.y = fmaf(s,u.y,acc.y); acc.z = fmaf(s,u.z,acc.z); acc.w = fmaf(s,u.w,acc.w); }
            else          { acc.x += u.x; acc.y += u.y; acc.z += u.z; acc.w += u.w; }
        }
        if (rem > 1) {
            float4 u = F4[c.y * 16 + lane];
            float s = PRESCALE ? g_dinv[c.y] : 1.0f;
            if (PRESCALE) { acc.x = fmaf(s,u.x,acc.x); acc.y = fmaf(s,u.y,acc.y); acc.z = fmaf(s,u.z,acc.z); acc.w = fmaf(s,u.w,acc.w); }
            else          { acc.x += u.x; acc.y += u.y; acc.z += u.z; acc.w += u.w; }
        }
        if (rem > 2) {
            float4 u = F4[c.z * 16 + lane];
            float s = PRESCALE ? g_dinv[c.z] : 1.0f;
            if (PRESCALE) { acc.x = fmaf(s,u.x,acc.x); acc.y = fmaf(s,u.y,acc.y); acc.z = fmaf(s,u.z,acc.z); acc.w = fmaf(s,u.w,acc.w); }
            else          { acc.x += u.x; acc.y += u.y; acc.z += u.z; acc.w += u.w; }
        }
    }
    float4 o;
    if (FINISH) {
        float4 bb = reinterpret_cast<const float4*>(bias)[lane];
        o.x = fmaf(di, acc.x, bb.x);
        o.y = fmaf(di, acc.y, bb.y);
        o.z = fmaf(di, acc.z, bb.z);
        o.w = fmaf(di, acc.w, bb.w);
    } else {
        o = acc;
    }
    reinterpret_cast<float4*>(O)[node * 16 + lane] = o;
}

// ---------------- GEMM1: h = relu(b1 + dinv[r]*(z@W1))  [n,64]x[64,128] ----------------
// K-paired f32x2: Wt[j][k] in smem (stride 68, conflict-free LDS.128), A rows loaded
// directly as ulonglong2 (natural k-pairs). block (32,8), 8 rows/thread, 4 cols/thread.
#define W1_STRIDE 68
__global__ void __launch_bounds__(256) k_gemm1(
        const float* __restrict__ Z, const float* __restrict__ W,
        const float* __restrict__ b, float* __restrict__ H, int n) {
    __shared__ float Ws[128 * W1_STRIDE];
    int tid = threadIdx.y * 32 + threadIdx.x;
    for (int i = tid; i < 64 * 128; i += 256) {
        int k = i >> 7, j = i & 127;        // W[k][j], row-major [64,128]
        Ws[j * W1_STRIDE + k] = W[i];
    }
    __syncthreads();
    int tx = threadIdx.x;
    int r0 = blockIdx.x * 64 + threadIdx.y * 8;
    int rr[8];
    #pragma unroll
    for (int q = 0; q < 8; q++) rr[q] = min(r0 + q, n - 1);
    const ulonglong2* A2 = reinterpret_cast<const ulonglong2*>(Z);  // row = 16 x ull2
    u64 acc[8][4] = {};
    #pragma unroll
    for (int k4 = 0; k4 < 16; k4++) {
        ulonglong2 a[8];
        #pragma unroll
        for (int q = 0; q < 8; q++) a[q] = A2[rr[q] * 16 + k4];
        #pragma unroll
        for (int c = 0; c < 4; c++) {
            int col = c * 32 + tx;
            ulonglong2 w = *reinterpret_cast<const ulonglong2*>(&Ws[col * W1_STRIDE + k4 * 4]);
            #pragma unroll
            for (int q = 0; q < 8; q++) {
                fma2(acc[q][c], a[q].x, w.x);
                fma2(acc[q][c], a[q].y, w.y);
            }
        }
    }
    float bb[4];
    #pragma unroll
    for (int c = 0; c < 4; c++) bb[c] = b[c * 32 + tx];
    #pragma unroll
    for (int q = 0; q < 8; q++) {
        int r = r0 + q;
        if (r < n) {
            float s = g_dinv[r];
            #pragma unroll
            for (int c = 0; c < 4; c++) {
                float2 f = up(acc[q][c]);
                float v = f.x + f.y;
                H[(size_t)r * 128 + c * 32 + tx] = fmaxf(fmaf(s, v, bb[c]), 0.f);
            }
        }
    }
}

// ---------------- GEMM2: y2 = dinv[r]*(h@W2)  [n,128]x[128,64] ----------------
// block (16,16), 8 rows/thread, 4 cols/thread. Wt stride 132.
#define W2_STRIDE 132
__global__ void __launch_bounds__(256) k_gemm2(
        const float* __restrict__ H, const float* __restrict__ W,
        float* __restrict__ Y2, int n) {
    __shared__ float Ws[64 * W2_STRIDE];
    int tid = threadIdx.y * 16 + threadIdx.x;
    for (int i = tid; i < 128 * 64; i += 256) {
        int k = i >> 6, j = i & 63;         // W[k][j], row-major [128,64]
        Ws[j * W2_STRIDE + k] = W[i];
    }
    __syncthreads();
    int tx = threadIdx.x;
    int r0 = blockIdx.x * 128 + threadIdx.y * 8;
    int rr[8];
    #pragma unroll
    for (int q = 0; q < 8; q++) rr[q] = min(r0 + q, n - 1);
    const ulonglong2* A2 = reinterpret_cast<const ulonglong2*>(H);  // row = 32 x ull2
    u64 acc[8][4] = {};
    #pragma unroll
    for (int k4 = 0; k4 < 32; k4++) {
        ulonglong2 a[8];
        #pragma unroll
        for (int q = 0; q < 8; q++) a[q] = A2[rr[q] * 32 + k4];
        #pragma unroll
        for (int c = 0; c < 4; c++) {
            int col = c * 16 + tx;
            ulonglong2 w = *reinterpret_cast<const ulonglong2*>(&Ws[col * W2_STRIDE + k4 * 4]);
            #pragma unroll
            for (int q = 0; q < 8; q++) {
                fma2(acc[q][c], a[q].x, w.x);
                fma2(acc[q][c], a[q].y, w.y);
            }
        }
    }
    #pragma unroll
    for (int q = 0; q < 8; q++) {
        int r = r0 + q;
        if (r < n) {
            float s = g_dinv[r];
            #pragma unroll
            for (int c = 0; c < 4; c++) {
                float2 f = up(acc[q][c]);
                Y2[(size_t)r * 64 + c * 16 + tx] = s * (f.x + f.y);
            }
        }
    }
}

extern "C" void kernel_launch(void* const* d_in, const int* in_sizes, int n_in,
                              void* d_out, int out_size) {
    const float* x  = (const float*)d_in[0];
    const int*   ei = (const int*)  d_in[1];
    const float* W1 = (const float*)d_in[2];
    const float* b1 = (const float*)d_in[3];
    const float* W2 = (const float*)d_in[4];
    const float* b2 = (const float*)d_in[5];
    float* out = (float*)d_out;

    int n = in_sizes[0] / DIM_IN;   // 50000
    int e = in_sizes[1] / 2;        // 800000
    const int* src = ei;
    const int* dst = ei + e;

    float *z, *h, *y2;
    int* cnt;
    cudaGetSymbolAddress((void**)&z,   g_z);
    cudaGetSymbolAddress((void**)&h,   g_h);
    cudaGetSymbolAddress((void**)&y2,  g_y2);
    cudaGetSymbolAddress((void**)&cnt, g_cnt);

    const int TB = 256;

    // build
    cudaMemsetAsync(cnt, 0, (size_t)n * sizeof(int));
    k_place<<<(e + TB - 1) / TB, TB>>>(src, dst, e);
    k_dinv <<<(n + TB - 1) / TB, TB>>>(n);

    // layer 1: z = dinv_i*x_i + sum dinv_c*x_c  (prescale fused into gather)
    k_agg<true, false><<<(n + 31) / 32, dim3(16, 32)>>>(x, z, nullptr, n);
    k_gemm1<<<(n + 63) / 64, dim3(32, 8)>>>(z, W1, b1, h, n);

    // layer 2
    k_gemm2<<<(n + 127) / 128, dim3(16, 16)>>>(h, W2, y2, n);
    k_agg<false, true><<<(n + 31) / 32, dim3(16, 32)>>>(y2, out, b2, n);
}